// round 16
// baseline (speedup 1.0000x reference)
#include <cuda_runtime.h>
#include <cuda_bf16.h>
#include <cuda_fp16.h>
#include <math.h>
#include <stdint.h>

#define Bn 4
#define Cn 512
#define Ln 4096

// ---------------------------------------------------------------------------
// Scratch (static device globals; no allocation allowed)
// ---------------------------------------------------------------------------
__device__ float g_S[(size_t)Bn * Ln];                         // row sums of exp_un
__device__ __half g_Qt[(size_t)Bn * Ln * Cn];                  // fp16(Q^T) [b][i][c]
__device__ __half g_Kt[(size_t)Bn * Ln * Cn];                  // fp16(K^T) [b][j][c]
__device__ __half g_V[(size_t)Bn * Cn * Ln];                   // fp16(V*mask) [b][c][j]
__device__ __half g_P[(size_t)Bn * Ln * Ln];                   // fp16 exp_un [b][i][j]

// ---------------------------------------------------------------------------
// Base-ISA helpers (compute_103-safe: ldmatrix / mma.sync / cp.async)
// ---------------------------------------------------------------------------
__device__ __forceinline__ uint32_t smem_u32(const void* p) {
    uint32_t a;
    asm("{ .reg .u64 t; cvta.to.shared.u64 t, %1; cvt.u32.u64 %0, t; }" : "=r"(a) : "l"(p));
    return a;
}
__device__ __forceinline__ void ldsm_x4(uint32_t addr, uint32_t r[4]) {
    asm volatile("ldmatrix.sync.aligned.m8n8.x4.shared.b16 {%0,%1,%2,%3}, [%4];"
                 : "=r"(r[0]), "=r"(r[1]), "=r"(r[2]), "=r"(r[3]) : "r"(addr));
}
__device__ __forceinline__ void mma_f16(float d[4], const uint32_t a[4], const uint32_t b[2]) {
    asm volatile("mma.sync.aligned.m16n8k16.row.col.f32.f16.f16.f32 "
                 "{%0,%1,%2,%3}, {%4,%5,%6,%7}, {%8,%9}, {%0,%1,%2,%3};"
                 : "+f"(d[0]), "+f"(d[1]), "+f"(d[2]), "+f"(d[3])
                 : "r"(a[0]), "r"(a[1]), "r"(a[2]), "r"(a[3]), "r"(b[0]), "r"(b[1]));
}
#define CP16(d, s) asm volatile("cp.async.cg.shared.global [%0], [%1], 16;" :: "r"(d), "l"(s))
#define CP_COMMIT() asm volatile("cp.async.commit_group;" ::: "memory")
#define CP_WAIT1()  asm volatile("cp.async.wait_group 1;" ::: "memory")
#define CP_WAIT0()  asm volatile("cp.async.wait_group 0;" ::: "memory")

// ---------------------------------------------------------------------------
// smem geometry: 2 tiles (A, B), 128 rows x 64 fp16 = 128 B rows, canonical
// SW128 swizzle. Triple buffered: 3 x 32 KB = 96 KB; 128-reg cap -> 2 CTAs/SM.
// ---------------------------------------------------------------------------
#define SW(o) ((o) ^ (((o) >> 3) & 0x70))
#define ROWB 128
#define TILE_B (128 * ROWB)        // 16384
#define NSTAGE 3
#define BUFB (2 * TILE_B)          // 32768
#define LMOFF (NSTAGE * BUFB)      // 98304
#define SMEM_BYTES (LMOFF + 512)

// ---------------------------------------------------------------------------
// fp16 tensor-core GEMM: acc = A·B. 128x128 tile, BK=64, 256 threads,
// 8 warps with 32x64 warp tiles, 3-stage cp.async pipeline, and an
// 8-stage (ks,h) fragment pipeline double-buffered in registers.
// FIRST: P[i][j] = fp16( exp((Qt·Kt)*scale)*(mask+1e-6) ); row sums -> g_S
// !FIRST: out[c][i] = (Σ_j V'[c][j]·P[i][j]) / S_i
// ---------------------------------------------------------------------------
template <bool FIRST>
__global__ __launch_bounds__(256, 2) void mma_gemm_kernel(float* __restrict__ Dout,
                                                          const float* __restrict__ mask)
{
    constexpr int KTOT = FIRST ? Cn : Ln;
    constexpr int LD   = FIRST ? Cn : Ln;
    constexpr int NIT  = KTOT / 64;

    extern __shared__ char smem[];
    const uint32_t sbase = smem_u32(smem);
    const int tid = threadIdx.x;
    const int b = blockIdx.z;
    const int n0 = (FIRST ? blockIdx.x : blockIdx.y) * 128;
    const int m0 = (FIRST ? blockIdx.y : blockIdx.x) * 128;

    const __half* A = (FIRST ? g_Qt : g_V) + ((size_t)b * (FIRST ? Ln : Cn) + m0) * LD;
    const __half* B = (FIRST ? g_Kt : g_P) + ((size_t)b * Ln + n0) * LD;

    float* lmp = (float*)(smem + LMOFF);
    if (FIRST) {
        if (tid < 128) lmp[tid] = mask[(size_t)b * Ln + n0 + tid] + 1e-6f;
    } else {
        if (tid < 128) lmp[tid] = 1.0f / g_S[(size_t)b * Ln + n0 + tid];
    }

    const int lane = tid & 31, wid = tid >> 5;
    const int wm = wid & 3, wn = wid >> 2;         // warp tile: 32 (m) x 64 (n)
    const int quad = lane >> 3, qj = lane & 7;
    const int a_row = (quad & 1) * 8 + qj;
    const int a_kb  = (quad >> 1) * 16;
    const int b_row = (quad >> 1) * 8 + qj;
    const int b_kb  = (quad & 1) * 16;

    float acc[2][8][4];
#pragma unroll
    for (int fm = 0; fm < 2; fm++)
#pragma unroll
        for (int fn = 0; fn < 8; fn++)
#pragma unroll
            for (int e = 0; e < 4; e++) acc[fm][fn][e] = 0.0f;

    // ---- global->smem loader: precomputed swizzled offsets, pointer bump ----
    uint32_t ldo[4];
    const __half* pA[4];
    const __half* pB[4];
#pragma unroll
    for (int t = 0; t < 4; t++) {
        int f = t * 256 + tid;
        int row = f >> 3, ch = f & 7;
        ldo[t] = SW((uint32_t)(row * ROWB + ch * 16));
        pA[t] = A + (size_t)row * LD + ch * 8;
        pB[t] = B + (size_t)row * LD + ch * 8;
    }
    auto load_slab = [&](int buf) {
        const uint32_t bb = sbase + buf * BUFB;
#pragma unroll
        for (int t = 0; t < 4; t++) {
            CP16(bb + ldo[t],          pA[t]);
            CP16(bb + TILE_B + ldo[t], pB[t]);
        }
        CP_COMMIT();
#pragma unroll
        for (int t = 0; t < 4; t++) { pA[t] += 64; pB[t] += 64; }
    };

    load_slab(0);
    load_slab(1);

    // ---- fragment register pipeline ----------------------------------------
    uint32_t arp[2][2][4];   // [ks parity][fm][regs]
    uint32_t brp[2][4][2];   // [stage parity][n-frag][regs]

    int buf = 0;
    for (int it = 0; it < NIT; it++) {
        if (it + 1 < NIT) { CP_WAIT1(); } else { CP_WAIT0(); }
        __syncthreads();

        const uint32_t bb = sbase + buf * BUFB;
        auto ld_a = [&](int ks, int p) {
#pragma unroll
            for (int fm = 0; fm < 2; fm++) {
                uint32_t r = SW((uint32_t)((wm * 32 + fm * 16 + a_row) * ROWB + ks * 32 + a_kb));
                ldsm_x4(bb + r, arp[p][fm]);
            }
        };
        auto ld_b = [&](int ks, int h, int p) {
#pragma unroll
            for (int g = 0; g < 2; g++) {
                uint32_t r = SW((uint32_t)((wn * 64 + h * 32 + g * 16 + b_row) * ROWB + ks * 32 + b_kb));
                uint32_t t4[4];
                ldsm_x4(bb + TILE_B + r, t4);
                brp[p][g * 2][0] = t4[0]; brp[p][g * 2][1] = t4[1];
                brp[p][g * 2 + 1][0] = t4[2]; brp[p][g * 2 + 1][1] = t4[3];
            }
        };

        // prologue fragments for stage 0, then issue next slab's cp.async
        ld_a(0, 0);
        ld_b(0, 0, 0);
        if (it + 2 < NIT) {
            int nb = buf + 2; if (nb >= NSTAGE) nb -= NSTAGE;
            load_slab(nb);
        }

#pragma unroll
        for (int s = 0; s < 8; s++) {
            const int ks = s >> 1, h = s & 1;
            const int p = s & 1, ka = ks & 1;
            if (s < 7) {
                const int ns = s + 1, nks = ns >> 1, nh = ns & 1;
                if (nh == 0) ld_a(nks, nks & 1);
                ld_b(nks, nh, ns & 1);
            }
#pragma unroll
            for (int fm = 0; fm < 2; fm++)
#pragma unroll
                for (int fl = 0; fl < 4; fl++)
                    mma_f16(acc[fm][h * 4 + fl], arp[ka][fm], brp[p][fl]);
        }
        if (++buf == NSTAGE) buf = 0;
    }

    const float scale = 0.04419417382415922f;      // 1/sqrt(512)
    if (FIRST) {
        float* S = g_S + (size_t)b * Ln;
        __half* P = g_P + (size_t)b * Ln * Ln;
#pragma unroll
        for (int fm = 0; fm < 2; fm++) {
            const int r0 = m0 + wm * 32 + fm * 16 + (lane >> 2);
            float rs0 = 0.0f, rs1 = 0.0f;
#pragma unroll
            for (int fn = 0; fn < 8; fn++) {
                int cl = wn * 64 + fn * 8 + (lane & 3) * 2;
                float me0 = lmp[cl], me1 = lmp[cl + 1];
                float v0 = __expf(acc[fm][fn][0] * scale) * me0;
                float v1 = __expf(acc[fm][fn][1] * scale) * me1;
                float v2 = __expf(acc[fm][fn][2] * scale) * me0;
                float v3 = __expf(acc[fm][fn][3] * scale) * me1;
                rs0 += v0 + v1;
                rs1 += v2 + v3;
                size_t o0 = (size_t)r0 * Ln + n0 + cl;
                size_t o1 = (size_t)(r0 + 8) * Ln + n0 + cl;
                *(__half2*)&P[o0] = __floats2half2_rn(v0, v1);
                *(__half2*)&P[o1] = __floats2half2_rn(v2, v3);
            }
            rs0 += __shfl_xor_sync(0xffffffffu, rs0, 1);
            rs0 += __shfl_xor_sync(0xffffffffu, rs0, 2);
            rs1 += __shfl_xor_sync(0xffffffffu, rs1, 1);
            rs1 += __shfl_xor_sync(0xffffffffu, rs1, 2);
            if ((lane & 3) == 0) {
                atomicAdd(&S[r0], rs0);
                atomicAdd(&S[r0 + 8], rs1);
            }
        }
    } else {
        float* D = Dout + (size_t)b * Cn * Ln;
#pragma unroll
        for (int fm = 0; fm < 2; fm++)
#pragma unroll
            for (int fn = 0; fn < 8; fn++) {
                int r0 = m0 + wm * 32 + fm * 16 + (lane >> 2);
                int cl = wn * 64 + fn * 8 + (lane & 3) * 2;
                float i0 = lmp[cl], i1 = lmp[cl + 1];
                *(float2*)&D[(size_t)r0 * Ln + n0 + cl] =
                    make_float2(acc[fm][fn][0] * i0, acc[fm][fn][1] * i1);
                *(float2*)&D[(size_t)(r0 + 8) * Ln + n0 + cl] =
                    make_float2(acc[fm][fn][2] * i0, acc[fm][fn][3] * i1);
            }
    }
}

// ---------------------------------------------------------------------------
// Convert + transpose Q and K in one launch: [b][C][L] fp32 -> [b][L][C] fp16.
// grid z carries (b, which): z = b*2 + (0=Q, 1=K).
// ---------------------------------------------------------------------------
__global__ void convT_kernel(const float* __restrict__ Q, const float* __restrict__ K)
{
    __shared__ float tile[32][33];
    const int z = blockIdx.z;
    const int b = z >> 1;
    const bool isQ = (z & 1) == 0;
    const float* X = isQ ? Q : K;
    __half* Dst = isQ ? g_Qt : g_Kt;
    const int l0 = blockIdx.x * 32, c0 = blockIdx.y * 32;
    const int tx = threadIdx.x, ty = threadIdx.y;
#pragma unroll
    for (int r = 0; r < 32; r += 8)
        tile[ty + r][tx] = X[((size_t)b * Cn + c0 + ty + r) * Ln + l0 + tx];
    __syncthreads();
#pragma unroll
    for (int r = 0; r < 32; r += 8) {
        size_t idx = ((size_t)b * Ln + l0 + ty + r) * Cn + c0 + tx;
        Dst[idx] = __float2half(tile[tx][ty + r]);
    }
}

// Convert V: fp32 -> fp16 of V*mask (mask folded in). Also zeroes g_S.
__global__ void convV_kernel(const float* __restrict__ V, const float* __restrict__ mask)
{
    if (blockIdx.x < (Bn * Ln) / 256)
        g_S[(size_t)blockIdx.x * 256 + threadIdx.x] = 0.0f;
    size_t idx = ((size_t)blockIdx.x * 256 + threadIdx.x) * 2;
    const int b = (int)(idx / ((size_t)Cn * Ln));
    const int j = (int)(idx % Ln);
    float2 v = *(const float2*)(V + idx);
    float2 m = *(const float2*)(mask + (size_t)b * Ln + j);
    *(__half2*)(g_V + idx) = __floats2half2_rn(v.x * m.x, v.y * m.y);
}

// ---------------------------------------------------------------------------
// attOut: attention output only.
//   attT[b][j][i] = P[i][j] * (1/S_i) * mask_j    (64x64 smem transpose)
// ---------------------------------------------------------------------------
__global__ __launch_bounds__(256) void attOut_kernel(float* __restrict__ AT,
                                                     const float* __restrict__ mask)
{
    __shared__ float tile[64][65];
    __shared__ float sinv[64], smask[64];
    const int b = blockIdx.z, j0 = blockIdx.x * 64, i0 = blockIdx.y * 64;
    const int t = threadIdx.x;
    const int r = t >> 2;            // 0..63 (row i0+r)
    const int seg = t & 3;           // 16 contiguous j's each

    if (t < 64)       sinv[t] = 1.0f / g_S[(size_t)b * Ln + i0 + t];
    else if (t < 128) smask[t - 64] = mask[(size_t)b * Ln + j0 + (t - 64)];
    __syncthreads();

    {
        size_t src = ((size_t)b * Ln + i0 + r) * Ln + j0 + seg * 16;
        uint4 p0 = *(const uint4*)&g_P[src];
        uint4 p1 = *(const uint4*)&g_P[src + 8];
        const uint32_t* pw  = (const uint32_t*)&p0;
        const uint32_t* pw1 = (const uint32_t*)&p1;
        const float inv = sinv[r];
#pragma unroll
        for (int k = 0; k < 4; k++) {
            float2 hp = __half22float2(*(__half2*)&pw[k]);
            tile[r][seg * 16 + 2 * k]     = hp.x * inv * smask[seg * 16 + 2 * k];
            tile[r][seg * 16 + 2 * k + 1] = hp.y * inv * smask[seg * 16 + 2 * k + 1];
        }
#pragma unroll
        for (int k = 0; k < 4; k++) {
            float2 hp = __half22float2(*(__half2*)&pw1[k]);
            tile[r][seg * 16 + 8 + 2 * k]     = hp.x * inv * smask[seg * 16 + 8 + 2 * k];
            tile[r][seg * 16 + 8 + 2 * k + 1] = hp.y * inv * smask[seg * 16 + 8 + 2 * k + 1];
        }
    }
    __syncthreads();

    float o[16];
#pragma unroll
    for (int k = 0; k < 16; k++)
        o[k] = tile[seg * 16 + k][r];
    float* dst = AT + ((size_t)b * Ln + j0 + r) * Ln + i0 + seg * 16;
#pragma unroll
    for (int q = 0; q < 4; q++)
        *(float4*)&dst[q * 4] = *(float4*)&o[q * 4];
}

// ---------------------------------------------------------------------------
extern "C" void kernel_launch(void* const* d_in, const int* in_sizes, int n_in,
                              void* d_out, int out_size)
{
    const float* Q    = (const float*)d_in[0];
    const float* Kt   = (const float*)d_in[1];
    const float* V    = (const float*)d_in[2];
    const float* mask = (const float*)d_in[3];

    float* out  = (float*)d_out;                   // (B, C, L)
    float* attT = out + (size_t)Bn * Cn * Ln;      // (B, L, L)

    cudaFuncSetAttribute(mma_gemm_kernel<true>,
                         cudaFuncAttributeMaxDynamicSharedMemorySize, SMEM_BYTES);
    cudaFuncSetAttribute(mma_gemm_kernel<false>,
                         cudaFuncAttributeMaxDynamicSharedMemorySize, SMEM_BYTES);

    convT_kernel<<<dim3(Ln / 32, Cn / 32, 2 * Bn), dim3(32, 8)>>>(Q, Kt);
    convV_kernel<<<(int)(((size_t)Bn * Cn * Ln) / 512), 256>>>(V, mask);

    mma_gemm_kernel<true><<<dim3(Ln / 128, Ln / 128, Bn), 256, SMEM_BYTES>>>(nullptr, mask);
    mma_gemm_kernel<false><<<dim3(Cn / 128, Ln / 128, Bn), 256, SMEM_BYTES>>>(out, nullptr);
    attOut_kernel<<<dim3(Ln / 64, Ln / 64, Bn), 256>>>(attT, mask);
}

// round 17
// speedup vs baseline: 1.1285x; 1.1285x over previous
#include <cuda_runtime.h>
#include <cuda_bf16.h>
#include <cuda_fp16.h>
#include <math.h>
#include <stdint.h>

#define Bn 4
#define Cn 512
#define Ln 4096

// ---------------------------------------------------------------------------
// Scratch (static device globals; no allocation allowed)
// ---------------------------------------------------------------------------
__device__ float g_S[(size_t)Bn * Ln];                         // row sums of exp_un
__device__ __half g_Qt[(size_t)Bn * Ln * Cn];                  // fp16(Q^T) [b][i][c]
__device__ __half g_Kt[(size_t)Bn * Ln * Cn];                  // fp16(K^T) [b][j][c]
__device__ __half g_V[(size_t)Bn * Cn * Ln];                   // fp16(V*mask) [b][c][j]
__device__ __half g_P[(size_t)Bn * Ln * Ln];                   // fp16 exp_un [b][i][j]

// ---------------------------------------------------------------------------
// Base-ISA helpers (compute_103-safe: ldmatrix / mma.sync / cp.async)
// ---------------------------------------------------------------------------
__device__ __forceinline__ uint32_t smem_u32(const void* p) {
    uint32_t a;
    asm("{ .reg .u64 t; cvta.to.shared.u64 t, %1; cvt.u32.u64 %0, t; }" : "=r"(a) : "l"(p));
    return a;
}
__device__ __forceinline__ void ldsm_x4(uint32_t addr, uint32_t r[4]) {
    asm volatile("ldmatrix.sync.aligned.m8n8.x4.shared.b16 {%0,%1,%2,%3}, [%4];"
                 : "=r"(r[0]), "=r"(r[1]), "=r"(r[2]), "=r"(r[3]) : "r"(addr));
}
__device__ __forceinline__ void mma_f16(float d[4], const uint32_t a[4], const uint32_t b[2]) {
    asm volatile("mma.sync.aligned.m16n8k16.row.col.f32.f16.f16.f32 "
                 "{%0,%1,%2,%3}, {%4,%5,%6,%7}, {%8,%9}, {%0,%1,%2,%3};"
                 : "+f"(d[0]), "+f"(d[1]), "+f"(d[2]), "+f"(d[3])
                 : "r"(a[0]), "r"(a[1]), "r"(a[2]), "r"(a[3]), "r"(b[0]), "r"(b[1]));
}
#define CP16(d, s) asm volatile("cp.async.cg.shared.global [%0], [%1], 16;" :: "r"(d), "l"(s))
#define CP_COMMIT() asm volatile("cp.async.commit_group;" ::: "memory")
#define CP_WAIT1()  asm volatile("cp.async.wait_group 1;" ::: "memory")
#define CP_WAIT0()  asm volatile("cp.async.wait_group 0;" ::: "memory")

// ---------------------------------------------------------------------------
// smem geometry: 2 tiles (A, B), 128 rows x 64 fp16 = 128 B rows, canonical
// SW128 swizzle. Triple buffered: 3 x 32 KB = 96 KB; 128-reg cap -> 2 CTAs/SM.
// ---------------------------------------------------------------------------
#define SW(o) ((o) ^ (((o) >> 3) & 0x70))
#define ROWB 128
#define TILE_B (128 * ROWB)        // 16384
#define NSTAGE 3
#define BUFB (2 * TILE_B)          // 32768
#define LMOFF (NSTAGE * BUFB)      // 98304
#define SMEM_BYTES (LMOFF + 512)

// ---------------------------------------------------------------------------
// fp16 tensor-core GEMM: acc = A·B. 128x128 tile, BK=64, 256 threads,
// 8 warps with 32x64 warp tiles, 3-stage cp.async pipeline.
// FIRST: P[i][j] = fp16( exp((Qt·Kt)*scale)*(mask+1e-6) ); row sums -> g_S
// !FIRST: out[c][i] = (Σ_j V'[c][j]·P[i][j]) / S_i, and the attention output
//         attT[j][i] = P[i][j]·(1/S_i)·mask_j is written from the staged P
//         tiles (each of the 4 c-tile CTAs covers a 16-row j slice).
// ---------------------------------------------------------------------------
template <bool FIRST>
__global__ __launch_bounds__(256, 2) void mma_gemm_kernel(float* __restrict__ Dout,
                                                          float* __restrict__ AT,
                                                          const float* __restrict__ mask)
{
    constexpr int KTOT = FIRST ? Cn : Ln;
    constexpr int LD   = FIRST ? Cn : Ln;
    constexpr int NIT  = KTOT / 64;

    extern __shared__ char smem[];
    const uint32_t sbase = smem_u32(smem);
    const int tid = threadIdx.x;
    const int b = blockIdx.z;
    const int n0 = (FIRST ? blockIdx.x : blockIdx.y) * 128;
    const int m0 = (FIRST ? blockIdx.y : blockIdx.x) * 128;

    const __half* A = (FIRST ? g_Qt : g_V) + ((size_t)b * (FIRST ? Ln : Cn) + m0) * LD;
    const __half* B = (FIRST ? g_Kt : g_P) + ((size_t)b * Ln + n0) * LD;

    float* lmp = (float*)(smem + LMOFF);
    if (FIRST) {
        if (tid < 128) lmp[tid] = mask[(size_t)b * Ln + n0 + tid] + 1e-6f;
    } else {
        if (tid < 128) lmp[tid] = 1.0f / g_S[(size_t)b * Ln + n0 + tid];
    }

    const int lane = tid & 31, wid = tid >> 5;
    const int wm = wid & 3, wn = wid >> 2;         // warp tile: 32 (m) x 64 (n)
    const int quad = lane >> 3, qj = lane & 7;
    const int a_row = (quad & 1) * 8 + qj;
    const int a_kb  = (quad >> 1) * 16;
    const int b_row = (quad >> 1) * 8 + qj;
    const int b_kb  = (quad & 1) * 16;

    float acc[2][8][4];
#pragma unroll
    for (int fm = 0; fm < 2; fm++)
#pragma unroll
        for (int fn = 0; fn < 8; fn++)
#pragma unroll
            for (int e = 0; e < 4; e++) acc[fm][fn][e] = 0.0f;

    // ---- global->smem loader: precomputed swizzled offsets, pointer bump ----
    uint32_t ldo[4];
    const __half* pA[4];
    const __half* pB[4];
#pragma unroll
    for (int t = 0; t < 4; t++) {
        int f = t * 256 + tid;
        int row = f >> 3, ch = f & 7;
        ldo[t] = SW((uint32_t)(row * ROWB + ch * 16));
        pA[t] = A + (size_t)row * LD + ch * 8;
        pB[t] = B + (size_t)row * LD + ch * 8;
    }
    auto load_slab = [&](int buf) {
        const uint32_t bb = sbase + buf * BUFB;
#pragma unroll
        for (int t = 0; t < 4; t++) {
            CP16(bb + ldo[t],          pA[t]);
            CP16(bb + TILE_B + ldo[t], pB[t]);
        }
        CP_COMMIT();
#pragma unroll
        for (int t = 0; t < 4; t++) { pA[t] += 64; pB[t] += 64; }
    };

    load_slab(0);
    load_slab(1);

    // attT-fusion constants (GEMM2 only)
    const int at_jl = (FIRST ? 0 : (int)blockIdx.x * 16) + (tid >> 4);  // j within BK=64
    const int at_i  = tid & 15;                                         // i base
    const float* mrow = mask + (size_t)b * Ln;

    int buf = 0;
    for (int it = 0; it < NIT; it++) {
        if (it + 1 < NIT) { CP_WAIT1(); } else { CP_WAIT0(); }
        __syncthreads();
        if (it + 2 < NIT) {
            int nb = buf + 2; if (nb >= NSTAGE) nb -= NSTAGE;
            load_slab(nb);
        }

        const uint32_t bb = sbase + buf * BUFB;
#pragma unroll
        for (int ks = 0; ks < 4; ks++) {
            uint32_t ar[2][4];
#pragma unroll
            for (int fm = 0; fm < 2; fm++) {
                uint32_t r = SW((uint32_t)((wm * 32 + fm * 16 + a_row) * ROWB + ks * 32 + a_kb));
                ldsm_x4(bb + r, ar[fm]);
            }
#pragma unroll
            for (int h = 0; h < 2; h++) {
                uint32_t br[4][2];
#pragma unroll
                for (int g = 0; g < 2; g++) {
                    uint32_t r = SW((uint32_t)((wn * 64 + h * 32 + g * 16 + b_row) * ROWB + ks * 32 + b_kb));
                    uint32_t t4[4];
                    ldsm_x4(bb + TILE_B + r, t4);
                    br[g * 2][0] = t4[0]; br[g * 2][1] = t4[1];
                    br[g * 2 + 1][0] = t4[2]; br[g * 2 + 1][1] = t4[3];
                }
#pragma unroll
                for (int fm = 0; fm < 2; fm++)
#pragma unroll
                    for (int fl = 0; fl < 4; fl++)
                        mma_f16(acc[fm][h * 4 + fl], ar[fm], br[fl]);
            }
        }

        if (!FIRST) {
            // write attT slice for this P tile: j = k0 + at_jl, i = n0 + at_i + 16e.
            const int k0 = it * 64;
            const float mj = mrow[k0 + at_jl];
            float* dst = AT + ((size_t)b * Ln + k0 + at_jl) * Ln + n0 + at_i;
            const uint32_t pb = bb + TILE_B;
#pragma unroll
            for (int e = 0; e < 8; e++) {
                const int il = at_i + 16 * e;
                __half hv;
                uint32_t ra = pb + SW((uint32_t)(il * ROWB + at_jl * 2));
                asm volatile("ld.shared.b16 %0, [%1];" : "=h"(*(uint16_t*)&hv) : "r"(ra));
                dst[16 * e] = __half2float(hv) * lmp[il] * mj;
            }
        }
        if (++buf == NSTAGE) buf = 0;
    }

    const float scale = 0.04419417382415922f;      // 1/sqrt(512)
    if (FIRST) {
        float* S = g_S + (size_t)b * Ln;
        __half* P = g_P + (size_t)b * Ln * Ln;
#pragma unroll
        for (int fm = 0; fm < 2; fm++) {
            const int r0 = m0 + wm * 32 + fm * 16 + (lane >> 2);
            float rs0 = 0.0f, rs1 = 0.0f;
#pragma unroll
            for (int fn = 0; fn < 8; fn++) {
                int cl = wn * 64 + fn * 8 + (lane & 3) * 2;
                float me0 = lmp[cl], me1 = lmp[cl + 1];
                float v0 = __expf(acc[fm][fn][0] * scale) * me0;
                float v1 = __expf(acc[fm][fn][1] * scale) * me1;
                float v2 = __expf(acc[fm][fn][2] * scale) * me0;
                float v3 = __expf(acc[fm][fn][3] * scale) * me1;
                rs0 += v0 + v1;
                rs1 += v2 + v3;
                size_t o0 = (size_t)r0 * Ln + n0 + cl;
                size_t o1 = (size_t)(r0 + 8) * Ln + n0 + cl;
                *(__half2*)&P[o0] = __floats2half2_rn(v0, v1);
                *(__half2*)&P[o1] = __floats2half2_rn(v2, v3);
            }
            rs0 += __shfl_xor_sync(0xffffffffu, rs0, 1);
            rs0 += __shfl_xor_sync(0xffffffffu, rs0, 2);
            rs1 += __shfl_xor_sync(0xffffffffu, rs1, 1);
            rs1 += __shfl_xor_sync(0xffffffffu, rs1, 2);
            if ((lane & 3) == 0) {
                atomicAdd(&S[r0], rs0);
                atomicAdd(&S[r0 + 8], rs1);
            }
        }
    } else {
        float* D = Dout + (size_t)b * Cn * Ln;
#pragma unroll
        for (int fm = 0; fm < 2; fm++)
#pragma unroll
            for (int fn = 0; fn < 8; fn++) {
                int r0 = m0 + wm * 32 + fm * 16 + (lane >> 2);
                int cl = wn * 64 + fn * 8 + (lane & 3) * 2;
                float i0 = lmp[cl], i1 = lmp[cl + 1];
                *(float2*)&D[(size_t)r0 * Ln + n0 + cl] =
                    make_float2(acc[fm][fn][0] * i0, acc[fm][fn][1] * i1);
                *(float2*)&D[(size_t)(r0 + 8) * Ln + n0 + cl] =
                    make_float2(acc[fm][fn][2] * i0, acc[fm][fn][3] * i1);
            }
    }
}

// ---------------------------------------------------------------------------
// Convert + transpose Q and K in one launch: [b][C][L] fp32 -> [b][L][C] fp16.
// grid z carries (b, which): z = b*2 + (0=Q, 1=K).
// ---------------------------------------------------------------------------
__global__ void convT_kernel(const float* __restrict__ Q, const float* __restrict__ K)
{
    __shared__ float tile[32][33];
    const int z = blockIdx.z;
    const int b = z >> 1;
    const bool isQ = (z & 1) == 0;
    const float* X = isQ ? Q : K;
    __half* Dst = isQ ? g_Qt : g_Kt;
    const int l0 = blockIdx.x * 32, c0 = blockIdx.y * 32;
    const int tx = threadIdx.x, ty = threadIdx.y;
#pragma unroll
    for (int r = 0; r < 32; r += 8)
        tile[ty + r][tx] = X[((size_t)b * Cn + c0 + ty + r) * Ln + l0 + tx];
    __syncthreads();
#pragma unroll
    for (int r = 0; r < 32; r += 8) {
        size_t idx = ((size_t)b * Ln + l0 + ty + r) * Cn + c0 + tx;
        Dst[idx] = __float2half(tile[tx][ty + r]);
    }
}

// Convert V: fp32 -> fp16 of V*mask (mask folded in). Also zeroes g_S.
__global__ void convV_kernel(const float* __restrict__ V, const float* __restrict__ mask)
{
    if (blockIdx.x < (Bn * Ln) / 256)
        g_S[(size_t)blockIdx.x * 256 + threadIdx.x] = 0.0f;
    size_t idx = ((size_t)blockIdx.x * 256 + threadIdx.x) * 2;
    const int b = (int)(idx / ((size_t)Cn * Ln));
    const int j = (int)(idx % Ln);
    float2 v = *(const float2*)(V + idx);
    float2 m = *(const float2*)(mask + (size_t)b * Ln + j);
    *(__half2*)(g_V + idx) = __floats2half2_rn(v.x * m.x, v.y * m.y);
}

// ---------------------------------------------------------------------------
extern "C" void kernel_launch(void* const* d_in, const int* in_sizes, int n_in,
                              void* d_out, int out_size)
{
    const float* Q    = (const float*)d_in[0];
    const float* Kt   = (const float*)d_in[1];
    const float* V    = (const float*)d_in[2];
    const float* mask = (const float*)d_in[3];

    float* out  = (float*)d_out;                   // (B, C, L)
    float* attT = out + (size_t)Bn * Cn * Ln;      // (B, L, L)

    cudaFuncSetAttribute(mma_gemm_kernel<true>,
                         cudaFuncAttributeMaxDynamicSharedMemorySize, SMEM_BYTES);
    cudaFuncSetAttribute(mma_gemm_kernel<false>,
                         cudaFuncAttributeMaxDynamicSharedMemorySize, SMEM_BYTES);

    convT_kernel<<<dim3(Ln / 32, Cn / 32, 2 * Bn), dim3(32, 8)>>>(Q, Kt);
    convV_kernel<<<(int)(((size_t)Bn * Cn * Ln) / 512), 256>>>(V, mask);

    mma_gemm_kernel<true><<<dim3(Ln / 128, Ln / 128, Bn), 256, SMEM_BYTES>>>(nullptr, nullptr, mask);
    mma_gemm_kernel<false><<<dim3(Cn / 128, Ln / 128, Bn), 256, SMEM_BYTES>>>(out, attT, mask);
}